// round 14
// baseline (speedup 1.0000x reference)
#include <cuda_runtime.h>
#include <math.h>

#define B_  4
#define S_  1024
#define D_  768
#define H_  384
#define NROW (B_*S_)            // 4096
#define BOND_ 3.8f
#define LR_ 0.01f
#define BETA1_ 0.9f
#define BETA2_ 0.999f
#define ADAM_EPS_ 1e-8f
#define NSTEPS_ 50

typedef unsigned long long ull;

// ---------- packed f32x2 helpers (Blackwell FFMA2 path) ----------
__device__ __forceinline__ ull pk2(float lo, float hi) {
    ull r; asm("mov.b64 %0,{%1,%2};" : "=l"(r) : "f"(lo), "f"(hi)); return r;
}
__device__ __forceinline__ void upk2(ull v, float& lo, float& hi) {
    asm("mov.b64 {%0,%1},%2;" : "=f"(lo), "=f"(hi) : "l"(v));
}
__device__ __forceinline__ ull fma2(ull a, ull b, ull c) {
    ull r; asm("fma.rn.f32x2 %0,%1,%2,%3;" : "=l"(r) : "l"(a), "l"(b), "l"(c)); return r;
}
__device__ __forceinline__ ull mul2(ull a, ull b) {
    ull r; asm("mul.rn.f32x2 %0,%1,%2;" : "=l"(r) : "l"(a), "l"(b)); return r;
}
__device__ __forceinline__ float rsq(float x) {
    float r; asm("rsqrt.approx.f32 %0,%1;" : "=f"(r) : "f"(x)); return r;
}
__device__ __forceinline__ float sqa(float x) {
    float r; asm("sqrt.approx.f32 %0,%1;" : "=f"(r) : "f"(x)); return r;
}
__device__ __forceinline__ float rcpa(float x) {
    float r; asm("rcp.approx.f32 %0,%1;" : "=f"(r) : "f"(x)); return r;
}

// ----- device scratch (no allocations allowed) -----
__device__ float g_h[NROW * H_];               // hidden after ReLU (6 MB)
__device__ float g_delta[NROW * 3];
__device__ float g_pA[3 * NROW];               // ping-pong positions, SoA planes x|y|z
__device__ float g_pB[3 * NROW];
__device__ float g_cms[(size_t)B_ * S_ * S_];  // symmetrized + prescaled contact map (16 MB)
__device__ unsigned g_flag[148 * 32];          // per-block step flags, 128B-strided slots

__device__ __forceinline__ unsigned ld_acq(const unsigned* p) {
    unsigned v;
    asm volatile("ld.acquire.gpu.global.u32 %0,[%1];" : "=r"(v) : "l"(p) : "memory");
    return v;
}
__device__ __forceinline__ void st_rel(unsigned* p, unsigned v) {
    asm volatile("st.release.gpu.global.u32 [%0],%1;" :: "l"(p), "r"(v) : "memory");
}

// =====================================================================
// K1a: g_h = ReLU(A[4096,768] @ W1[768,384] + b1)   (proven R9/R11 version)
// =====================================================================
__global__ __launch_bounds__(256) void gemm_relu_kernel(
    const float* __restrict__ A, const float* __restrict__ W1,
    const float* __restrict__ b1)
{
    __shared__ float As[16][64];
    __shared__ float Bs[16][64];

    const int tid = threadIdx.x;
    const int tx = tid & 15;
    const int ty = tid >> 4;
    const int m0 = blockIdx.y * 64;
    const int n0 = blockIdx.x * 64;

    ull acc[4][2];
#pragma unroll
    for (int i = 0; i < 4; i++) { acc[i][0] = 0ull; acc[i][1] = 0ull; }

    for (int k0 = 0; k0 < D_; k0 += 16) {
        {
            int row = tid >> 2;
            int c4  = tid & 3;
            float4 a = *(const float4*)(A + (size_t)(m0 + row) * D_ + k0 + c4 * 4);
            As[c4 * 4 + 0][row] = a.x;
            As[c4 * 4 + 1][row] = a.y;
            As[c4 * 4 + 2][row] = a.z;
            As[c4 * 4 + 3][row] = a.w;
        }
        {
            int row = tid >> 4;
            int c4  = tid & 15;
            *(float4*)&Bs[row][c4 * 4] =
                *(const float4*)(W1 + (size_t)(k0 + row) * H_ + n0 + c4 * 4);
        }
        __syncthreads();

#pragma unroll
        for (int k = 0; k < 16; k++) {
            float a[4], bb[4];
            *(float4*)a  = *(const float4*)&As[k][ty * 4];
            *(float4*)bb = *(const float4*)&Bs[k][tx * 4];
            ull b01 = pk2(bb[0], bb[1]);
            ull b23 = pk2(bb[2], bb[3]);
#pragma unroll
            for (int i = 0; i < 4; i++) {
                ull ai = pk2(a[i], a[i]);
                acc[i][0] = fma2(ai, b01, acc[i][0]);
                acc[i][1] = fma2(ai, b23, acc[i][1]);
            }
        }
        __syncthreads();
    }

    float4 bias = *(const float4*)(b1 + n0 + tx * 4);
#pragma unroll
    for (int i = 0; i < 4; i++) {
        float v0, v1, v2, v3;
        upk2(acc[i][0], v0, v1);
        upk2(acc[i][1], v2, v3);
        float4 o;
        o.x = fmaxf(v0 + bias.x, 0.f);
        o.y = fmaxf(v1 + bias.y, 0.f);
        o.z = fmaxf(v2 + bias.z, 0.f);
        o.w = fmaxf(v3 + bias.w, 0.f);
        *(float4*)(g_h + (size_t)(m0 + ty * 4 + i) * H_ + n0 + tx * 4) = o;
    }
}

// =====================================================================
// K1b: warp-per-row angles + delta. 512 blocks x 256 thr (8 warps).
// =====================================================================
__global__ __launch_bounds__(256) void angles_delta_kernel(
    const float* __restrict__ W2, const float* __restrict__ b2)
{
    const int w    = threadIdx.x >> 5;
    const int lane = threadIdx.x & 31;
    const int row  = blockIdx.x * 8 + w;
    const float* h = g_h + (size_t)row * H_;

    float a0 = 0.f, a1 = 0.f;
#pragma unroll
    for (int it = 0; it < H_ / 32; it++) {
        int j = it * 32 + lane;
        float hv = h[j];
        a0 = fmaf(hv, __ldg(W2 + j * 3 + 0), a0);
        a1 = fmaf(hv, __ldg(W2 + j * 3 + 1), a1);
    }
#pragma unroll
    for (int off = 16; off; off >>= 1) {
        a0 += __shfl_down_sync(0xffffffffu, a0, off);
        a1 += __shfl_down_sync(0xffffffffu, a1, off);
    }
    if (lane == 0) {
        float phi = a0 + b2[0];
        float psi = a1 + b2[1];
        float dx, dy, dz;
        if ((row & (S_ - 1)) == 0) {
            dx = dy = dz = 0.f;
        } else {
            float sp, cp, ss, cs;
            sincosf(phi, &sp, &cp);
            sincosf(psi, &ss, &cs);
            dx = BOND_ * cp * cs;
            dy = BOND_ * sp * cs;
            dz = BOND_ * ss;
        }
        g_delta[row * 3 + 0] = dx;
        g_delta[row * 3 + 1] = dy;
        g_delta[row * 3 + 2] = dz;
    }
}

// =====================================================================
// K2: inclusive cumsum per (batch, dim) -> g_pA SoA planes
// =====================================================================
__global__ __launch_bounds__(1024) void cumsum_kernel()
{
    const int b   = blockIdx.x / 3;
    const int dim = blockIdx.x % 3;
    const int s   = threadIdx.x;

    float v = g_delta[((b * S_) + s) * 3 + dim];
    int lane = s & 31, w = s >> 5;
#pragma unroll
    for (int off = 1; off < 32; off <<= 1) {
        float n = __shfl_up_sync(0xffffffffu, v, off);
        if (lane >= off) v += n;
    }
    __shared__ float wsum[32];
    if (lane == 31) wsum[w] = v;
    __syncthreads();
    if (w == 0) {
        float t = wsum[lane];
#pragma unroll
        for (int off = 1; off < 32; off <<= 1) {
            float n = __shfl_up_sync(0xffffffffu, t, off);
            if (lane >= off) t += n;
        }
        wsum[lane] = t;
    }
    __syncthreads();
    float excl = (w == 0) ? 0.f : wsum[w - 1];
    g_pA[dim * NROW + b * S_ + s] = v + excl;
}

// =====================================================================
// K0: cm_sym[b,i,j] = (cm[b,i,j] + cm[b,j,i]) / (B*S*S)
// =====================================================================
__global__ void cmsym_kernel(const float* __restrict__ cm)
{
    __shared__ float ts[32][33];
    const int b  = blockIdx.z;
    const int i0 = blockIdx.y * 32;
    const int j0 = blockIdx.x * 32;
    const float* cb = cm + (size_t)b * S_ * S_;
    float* ob = g_cms + (size_t)b * S_ * S_;
    const int tx = threadIdx.x, ty = threadIdx.y;
    const float invN = 1.0f / (float)((size_t)B_ * S_ * S_);

#pragma unroll
    for (int r = ty; r < 32; r += 8)
        ts[r][tx] = cb[(size_t)(j0 + r) * S_ + i0 + tx];
    __syncthreads();
#pragma unroll
    for (int r = ty; r < 32; r += 8)
        ob[(size_t)(i0 + r) * S_ + j0 + tx] =
            (cb[(size_t)(i0 + r) * S_ + j0 + tx] + ts[tx][r]) * invN;
}

// =====================================================================
// one (row, packed-j-pair) gradient step — f32x2; integer sign trick
// =====================================================================
struct PK {
    ull M1, EPS2;
};

__device__ __forceinline__ void pair_step(
    ull xj, ull yj, ull zj, ull cj,
    ull xi, ull yi, ull zi,
    ull& g0, ull& g1, ull& g2, const PK& K)
{
    ull dx = fma2(K.M1, xj, xi);
    ull dy = fma2(K.M1, yj, yi);
    ull dz = fma2(K.M1, zj, zi);
    ull d2 = fma2(dx, dx, K.EPS2);
    d2 = fma2(dy, dy, d2);
    d2 = fma2(dz, dz, d2);
    float dl, dh; upk2(d2, dl, dh);
    unsigned il = __float_as_uint(dl), ih = __float_as_uint(dh);
    unsigned csl = ((il - 0x42800000u) & 0x80000000u) ^ (unsigned)cj;
    unsigned csh = ((ih - 0x42800000u) & 0x80000000u) ^ (unsigned)(cj >> 32);
    ull cs = ((ull)csh << 32) | (ull)csl;
    ull inv = pk2(rsq(dl), rsq(dh));
    ull wg = mul2(cs, inv);
    g0 = fma2(wg, dx, g0);
    g1 = fma2(wg, dy, g1);
    g2 = fma2(wg, dz, g2);
}

// =====================================================================
// K3: persistent refine — 148 blocks (ALL SMs), 37 blocks/batch,
// <=28 rows/block (was 128 blocks x 32 rows with 20 SMs idle).
// Inner loop / barrier design identical to R11; barrier now 37 arrivals
// (lanes 0-4 spin on a second flag). smem: pos 12KB + 28 cm rows 112KB.
// =====================================================================
#define RTH 512
#define BPB 37      // blocks per batch
#define GRID_R (B_ * BPB)   // 148
#define MAXROWS 28
#define SMEM_REFINE ((3 * S_ + MAXROWS * S_) * (int)sizeof(float))

extern __shared__ float smref[];

__global__ __launch_bounds__(RTH, 1) void refine_kernel(float* __restrict__ out)
{
    float* xs  = smref;
    float* ys  = xs + S_;
    float* zs  = ys + S_;
    float* cmr = zs + S_;     // [28][1024]

    const int tid  = threadIdx.x;
    const int w    = tid >> 5;
    const int lane = tid & 31;
    const int b    = blockIdx.x / BPB;         // batch 0..3
    const int idx  = blockIdx.x % BPB;         // 0..36
    // first 25 blocks carry 28 rows, last 12 carry 27 (25*28 + 12*27 = 1024)
    const int base = (idx < 25) ? idx * 28 : (700 + (idx - 25) * 27);
    const int nr   = (idx < 25) ? 28 : 27;
    const bool hasA = (2 * w < nr);            // warps 0..13 (w13 maybe half)
    const bool hasB = (2 * w + 1 < nr);
    const int rA = base + w * 2;
    const int rB = hasB ? rA + 1 : rA;         // clamp for safe indexing

    // cache this warp's cm rows (once; reused 50 steps)
    if (hasA) {
        const float4* sA = (const float4*)(g_cms + ((size_t)b * S_ + rA) * S_);
        const float4* sB = (const float4*)(g_cms + ((size_t)b * S_ + rB) * S_);
        float4* dA = (float4*)(cmr + (size_t)(w * 2) * S_);
        float4* dB = (float4*)(cmr + (size_t)(w * 2 + 1) * S_);
        for (int k = lane; k < S_ / 4; k += 32) { dA[k] = sA[k]; dB[k] = sB[k]; }
    }

    // barrier state: my slot + per-lane peer slots (warp 0 waits).
    // 37 arrivals: lanes 0..31 watch flags 0..31; lanes 0..4 also 32..36.
    unsigned* myflag  = &g_flag[(unsigned)blockIdx.x * 32u];
    unsigned* pf1 = &g_flag[(unsigned)(b * BPB + lane) * 32u];
    unsigned* pf2 = &g_flag[(unsigned)(b * BPB + 32 + (lane < 5 ? lane : 0)) * 32u];
    unsigned mybase = 0, pb1 = 0, pb2 = 0;
    if (tid == 0) mybase = ld_acq(myflag);
    if (w == 0) {
        pb1 = ld_acq(pf1);
        if (lane < 5) pb2 = ld_acq(pf2);
    }

    float m[2][3] = {{0,0,0},{0,0,0}};
    float v[2][3] = {{0,0,0},{0,0,0}};
    float b1t = 1.f, b2t = 1.f;

    PK K;
    K.M1   = pk2(-1.f, -1.f);
    K.EPS2 = pk2(1e-12f, 1e-12f);

    const float* cApt = cmr + (size_t)(w * 2) * S_;
    const float* cBpt = cApt + S_;

    for (int t = 1; t <= NSTEPS_; t++) {
        const float* xin = (t & 1) ? g_pA : g_pB;
        float* xout      = (t & 1) ? g_pB : g_pA;

        // reload positions (L2-coherent)
        {
            const float4* px = (const float4*)(xin + 0 * NROW + b * S_);
            const float4* py = (const float4*)(xin + 1 * NROW + b * S_);
            const float4* pz = (const float4*)(xin + 2 * NROW + b * S_);
            for (int i = tid; i < S_ / 4; i += RTH) {
                ((float4*)xs)[i] = __ldcg(px + i);
                ((float4*)ys)[i] = __ldcg(py + i);
                ((float4*)zs)[i] = __ldcg(pz + i);
            }
        }
        __syncthreads();

        b1t *= BETA1_;
        b2t *= BETA2_;

        if (hasA) {
            const float axA = xs[rA], ayA = ys[rA], azA = zs[rA];
            const float axB = xs[rB], ayB = ys[rB], azB = zs[rB];
            const ull xiA = pk2(axA, axA), yiA = pk2(ayA, ayA), ziA = pk2(azA, azA);
            const ull xiB = pk2(axB, axB), yiB = pk2(ayB, ayB), ziB = pk2(azB, azB);

            ull gA0 = 0, gA1 = 0, gA2 = 0;
            ull gB0 = 0, gB1 = 0, gB2 = 0;

#pragma unroll
            for (int it = 0; it < 8; it++) {
                const int j = it * 128 + lane * 4;
                const ulonglong2 xj  = *(const ulonglong2*)(xs + j);
                const ulonglong2 yj  = *(const ulonglong2*)(ys + j);
                const ulonglong2 zj  = *(const ulonglong2*)(zs + j);
                const ulonglong2 cjA = *(const ulonglong2*)(cApt + j);
                const ulonglong2 cjB = *(const ulonglong2*)(cBpt + j);

                pair_step(xj.x, yj.x, zj.x, cjA.x, xiA, yiA, ziA, gA0, gA1, gA2, K);
                pair_step(xj.x, yj.x, zj.x, cjB.x, xiB, yiB, ziB, gB0, gB1, gB2, K);
                pair_step(xj.y, yj.y, zj.y, cjA.y, xiA, yiA, ziA, gA0, gA1, gA2, K);
                pair_step(xj.y, yj.y, zj.y, cjB.y, xiB, yiB, ziB, gB0, gB1, gB2, K);
            }

            float gr[2][3];
            {
                float lo, hi;
                upk2(gA0, lo, hi); gr[0][0] = lo + hi;
                upk2(gA1, lo, hi); gr[0][1] = lo + hi;
                upk2(gA2, lo, hi); gr[0][2] = lo + hi;
                upk2(gB0, lo, hi); gr[1][0] = lo + hi;
                upk2(gB1, lo, hi); gr[1][1] = lo + hi;
                upk2(gB2, lo, hi); gr[1][2] = lo + hi;
            }
#pragma unroll
            for (int off = 16; off; off >>= 1) {
                gr[0][0] += __shfl_down_sync(0xffffffffu, gr[0][0], off);
                gr[0][1] += __shfl_down_sync(0xffffffffu, gr[0][1], off);
                gr[0][2] += __shfl_down_sync(0xffffffffu, gr[0][2], off);
                gr[1][0] += __shfl_down_sync(0xffffffffu, gr[1][0], off);
                gr[1][1] += __shfl_down_sync(0xffffffffu, gr[1][1], off);
                gr[1][2] += __shfl_down_sync(0xffffffffu, gr[1][2], off);
            }

            if (lane == 0) {
                const float c1f = 1.f / (1.f - b1t);
                const float c2f = 1.f / (1.f - b2t);
                float px[2][3] = {{axA, ayA, azA}, {axB, ayB, azB}};
#pragma unroll
                for (int r = 0; r < 2; r++) {
                    float nv[3];
#pragma unroll
                    for (int d = 0; d < 3; d++) {
                        m[r][d] = BETA1_ * m[r][d] + (1.f - BETA1_) * gr[r][d];
                        v[r][d] = BETA2_ * v[r][d] + (1.f - BETA2_) * gr[r][d] * gr[r][d];
                        float den = sqa(v[r][d] * c2f) + ADAM_EPS_;
                        nv[d] = px[r][d] - LR_ * (m[r][d] * c1f) * rcpa(den);
                    }
                    if (r == 1 && !hasB) break;   // row B invalid: no store
                    const int row = (r == 0) ? rA : rB;
                    if (t == NSTEPS_) {
                        size_t o = ((size_t)b * S_ + row) * 3;
                        out[o + 0] = nv[0];
                        out[o + 1] = nv[1];
                        out[o + 2] = nv[2];
                    } else {
                        xout[0 * NROW + b * S_ + row] = nv[0];
                        xout[1 * NROW + b * S_ + row] = nv[1];
                        xout[2 * NROW + b * S_ + row] = nv[2];
                    }
                }
            }
        }

        if (t < NSTEPS_) {
            // bar.sync orders all warps' STGs before tid0's release-store
            __syncthreads();
            if (tid == 0) st_rel(myflag, mybase + (unsigned)t);
            if (w == 0) {
                const unsigned tg1 = pb1 + (unsigned)t;
                while (ld_acq(pf1) < tg1) { }
                if (lane < 5) {
                    const unsigned tg2 = pb2 + (unsigned)t;
                    while (ld_acq(pf2) < tg2) { }
                }
            }
            __syncthreads();
        }
    }
}

// =====================================================================
// host launcher (graph-capturable: kernel launches only, single stream)
// =====================================================================
extern "C" void kernel_launch(void* const* d_in, const int* in_sizes, int n_in,
                              void* d_out, int out_size)
{
    const float* bf  = (const float*)d_in[0];
    const float* cm  = (const float*)d_in[2];
    const float* Wb1 = (const float*)d_in[3];
    const float* bb1 = (const float*)d_in[4];
    const float* Wb2 = (const float*)d_in[5];
    const float* bb2 = (const float*)d_in[6];
    float* out = (float*)d_out;

    static int smem_set = 0;
    if (!smem_set) {
        cudaFuncSetAttribute(refine_kernel,
                             cudaFuncAttributeMaxDynamicSharedMemorySize, SMEM_REFINE);
        smem_set = 1;
    }

    gemm_relu_kernel<<<dim3(H_ / 64, NROW / 64), 256>>>(bf, Wb1, bb1);
    angles_delta_kernel<<<NROW / 8, 256>>>(Wb2, bb2);
    cmsym_kernel<<<dim3(S_ / 32, S_ / 32, B_), dim3(32, 8)>>>(cm);
    cumsum_kernel<<<B_ * 3, S_>>>();
    refine_kernel<<<GRID_R, RTH, SMEM_REFINE>>>(out);
}

// round 15
// speedup vs baseline: 1.2199x; 1.2199x over previous
#include <cuda_runtime.h>
#include <math.h>

#define B_  4
#define S_  1024
#define D_  768
#define H_  384
#define NROW (B_*S_)            // 4096
#define BOND_ 3.8f
#define LR_ 0.01f
#define BETA1_ 0.9f
#define BETA2_ 0.999f
#define ADAM_EPS_ 1e-8f
#define NSTEPS_ 50

typedef unsigned long long ull;

// ---------- packed f32x2 helpers (Blackwell FFMA2 path) ----------
__device__ __forceinline__ ull pk2(float lo, float hi) {
    ull r; asm("mov.b64 %0,{%1,%2};" : "=l"(r) : "f"(lo), "f"(hi)); return r;
}
__device__ __forceinline__ void upk2(ull v, float& lo, float& hi) {
    asm("mov.b64 {%0,%1},%2;" : "=f"(lo), "=f"(hi) : "l"(v));
}
__device__ __forceinline__ ull fma2(ull a, ull b, ull c) {
    ull r; asm("fma.rn.f32x2 %0,%1,%2,%3;" : "=l"(r) : "l"(a), "l"(b), "l"(c)); return r;
}
__device__ __forceinline__ ull mul2(ull a, ull b) {
    ull r; asm("mul.rn.f32x2 %0,%1,%2;" : "=l"(r) : "l"(a), "l"(b)); return r;
}
__device__ __forceinline__ float rsq(float x) {
    float r; asm("rsqrt.approx.f32 %0,%1;" : "=f"(r) : "f"(x)); return r;
}
__device__ __forceinline__ float sqa(float x) {
    float r; asm("sqrt.approx.f32 %0,%1;" : "=f"(r) : "f"(x)); return r;
}
__device__ __forceinline__ float rcpa(float x) {
    float r; asm("rcp.approx.f32 %0,%1;" : "=f"(r) : "f"(x)); return r;
}

// ----- device scratch (no allocations allowed) -----
__device__ float g_h[NROW * H_];               // hidden after ReLU (6 MB)
__device__ float g_delta[NROW * 3];
__device__ float g_pA[3 * NROW];               // ping-pong positions, SoA planes x|y|z
__device__ float g_pB[3 * NROW];
__device__ float g_cms[(size_t)B_ * S_ * S_];  // symmetrized + prescaled contact map (16 MB)
__device__ unsigned g_flag[128 * 32];          // per-block step flags, 128B-strided slots

__device__ __forceinline__ unsigned ld_acq(const unsigned* p) {
    unsigned v;
    asm volatile("ld.acquire.gpu.global.u32 %0,[%1];" : "=r"(v) : "l"(p) : "memory");
    return v;
}
__device__ __forceinline__ void st_rel(unsigned* p, unsigned v) {
    asm volatile("st.release.gpu.global.u32 [%0],%1;" :: "l"(p), "r"(v) : "memory");
}

// =====================================================================
// K1a: g_h = ReLU(A[4096,768] @ W1[768,384] + b1)   (proven R9/R11 version)
// =====================================================================
__global__ __launch_bounds__(256) void gemm_relu_kernel(
    const float* __restrict__ A, const float* __restrict__ W1,
    const float* __restrict__ b1)
{
    __shared__ float As[16][64];
    __shared__ float Bs[16][64];

    const int tid = threadIdx.x;
    const int tx = tid & 15;
    const int ty = tid >> 4;
    const int m0 = blockIdx.y * 64;
    const int n0 = blockIdx.x * 64;

    ull acc[4][2];
#pragma unroll
    for (int i = 0; i < 4; i++) { acc[i][0] = 0ull; acc[i][1] = 0ull; }

    for (int k0 = 0; k0 < D_; k0 += 16) {
        {
            int row = tid >> 2;
            int c4  = tid & 3;
            float4 a = *(const float4*)(A + (size_t)(m0 + row) * D_ + k0 + c4 * 4);
            As[c4 * 4 + 0][row] = a.x;
            As[c4 * 4 + 1][row] = a.y;
            As[c4 * 4 + 2][row] = a.z;
            As[c4 * 4 + 3][row] = a.w;
        }
        {
            int row = tid >> 4;
            int c4  = tid & 15;
            *(float4*)&Bs[row][c4 * 4] =
                *(const float4*)(W1 + (size_t)(k0 + row) * H_ + n0 + c4 * 4);
        }
        __syncthreads();

#pragma unroll
        for (int k = 0; k < 16; k++) {
            float a[4], bb[4];
            *(float4*)a  = *(const float4*)&As[k][ty * 4];
            *(float4*)bb = *(const float4*)&Bs[k][tx * 4];
            ull b01 = pk2(bb[0], bb[1]);
            ull b23 = pk2(bb[2], bb[3]);
#pragma unroll
            for (int i = 0; i < 4; i++) {
                ull ai = pk2(a[i], a[i]);
                acc[i][0] = fma2(ai, b01, acc[i][0]);
                acc[i][1] = fma2(ai, b23, acc[i][1]);
            }
        }
        __syncthreads();
    }

    float4 bias = *(const float4*)(b1 + n0 + tx * 4);
#pragma unroll
    for (int i = 0; i < 4; i++) {
        float v0, v1, v2, v3;
        upk2(acc[i][0], v0, v1);
        upk2(acc[i][1], v2, v3);
        float4 o;
        o.x = fmaxf(v0 + bias.x, 0.f);
        o.y = fmaxf(v1 + bias.y, 0.f);
        o.z = fmaxf(v2 + bias.z, 0.f);
        o.w = fmaxf(v3 + bias.w, 0.f);
        *(float4*)(g_h + (size_t)(m0 + ty * 4 + i) * H_ + n0 + tx * 4) = o;
    }
}

// =====================================================================
// K1b: per-row phi/psi = h @ W2[:,0:2] + b2, then delta vector
// =====================================================================
__global__ __launch_bounds__(128) void angles_delta_kernel(
    const float* __restrict__ W2, const float* __restrict__ b2)
{
    const int row = blockIdx.x;
    const int tid = threadIdx.x;
    const float* h = g_h + (size_t)row * H_;

    float a0 = 0.f, a1 = 0.f;
#pragma unroll
    for (int j = tid; j < H_; j += 128) {
        float hv = h[j];
        a0 = fmaf(hv, W2[j * 3 + 0], a0);
        a1 = fmaf(hv, W2[j * 3 + 1], a1);
    }
#pragma unroll
    for (int off = 16; off; off >>= 1) {
        a0 += __shfl_down_sync(0xffffffffu, a0, off);
        a1 += __shfl_down_sync(0xffffffffu, a1, off);
    }
    __shared__ float s0[4], s1[4];
    int w = tid >> 5, lane = tid & 31;
    if (lane == 0) { s0[w] = a0; s1[w] = a1; }
    __syncthreads();
    if (tid == 0) {
        float phi = s0[0] + s0[1] + s0[2] + s0[3] + b2[0];
        float psi = s1[0] + s1[1] + s1[2] + s1[3] + b2[1];
        float dx, dy, dz;
        if ((row & (S_ - 1)) == 0) {
            dx = dy = dz = 0.f;
        } else {
            float sp, cp, ss, cs;
            sincosf(phi, &sp, &cp);
            sincosf(psi, &ss, &cs);
            dx = BOND_ * cp * cs;
            dy = BOND_ * sp * cs;
            dz = BOND_ * ss;
        }
        g_delta[row * 3 + 0] = dx;
        g_delta[row * 3 + 1] = dy;
        g_delta[row * 3 + 2] = dz;
    }
}

// =====================================================================
// K2: inclusive cumsum per (batch, dim) -> g_pA SoA planes
// =====================================================================
__global__ __launch_bounds__(1024) void cumsum_kernel()
{
    const int b   = blockIdx.x / 3;
    const int dim = blockIdx.x % 3;
    const int s   = threadIdx.x;

    float v = g_delta[((b * S_) + s) * 3 + dim];
    int lane = s & 31, w = s >> 5;
#pragma unroll
    for (int off = 1; off < 32; off <<= 1) {
        float n = __shfl_up_sync(0xffffffffu, v, off);
        if (lane >= off) v += n;
    }
    __shared__ float wsum[32];
    if (lane == 31) wsum[w] = v;
    __syncthreads();
    if (w == 0) {
        float t = wsum[lane];
#pragma unroll
        for (int off = 1; off < 32; off <<= 1) {
            float n = __shfl_up_sync(0xffffffffu, t, off);
            if (lane >= off) t += n;
        }
        wsum[lane] = t;
    }
    __syncthreads();
    float excl = (w == 0) ? 0.f : wsum[w - 1];
    g_pA[dim * NROW + b * S_ + s] = v + excl;
}

// =====================================================================
// K0: cm_sym[b,i,j] = (cm[b,i,j] + cm[b,j,i]) / (B*S*S)
// =====================================================================
__global__ void cmsym_kernel(const float* __restrict__ cm)
{
    __shared__ float ts[32][33];
    const int b  = blockIdx.z;
    const int i0 = blockIdx.y * 32;
    const int j0 = blockIdx.x * 32;
    const float* cb = cm + (size_t)b * S_ * S_;
    float* ob = g_cms + (size_t)b * S_ * S_;
    const int tx = threadIdx.x, ty = threadIdx.y;
    const float invN = 1.0f / (float)((size_t)B_ * S_ * S_);

#pragma unroll
    for (int r = ty; r < 32; r += 8)
        ts[r][tx] = cb[(size_t)(j0 + r) * S_ + i0 + tx];
    __syncthreads();
#pragma unroll
    for (int r = ty; r < 32; r += 8)
        ob[(size_t)(i0 + r) * S_ + j0 + tx] =
            (cb[(size_t)(i0 + r) * S_ + j0 + tx] + ts[tx][r]) * invN;
}

// =====================================================================
// one (row, packed-j-pair) gradient step — f32x2; integer sign trick
// =====================================================================
struct PK {
    ull M1, EPS2;
};

__device__ __forceinline__ void pair_step(
    ull xj, ull yj, ull zj, ull cj,
    ull xi, ull yi, ull zi,
    ull& g0, ull& g1, ull& g2, const PK& K)
{
    ull dx = fma2(K.M1, xj, xi);
    ull dy = fma2(K.M1, yj, yi);
    ull dz = fma2(K.M1, zj, zi);
    ull d2 = fma2(dx, dx, K.EPS2);
    d2 = fma2(dy, dy, d2);
    d2 = fma2(dz, dz, d2);
    float dl, dh; upk2(d2, dl, dh);
    unsigned il = __float_as_uint(dl), ih = __float_as_uint(dh);
    unsigned csl = ((il - 0x42800000u) & 0x80000000u) ^ (unsigned)cj;
    unsigned csh = ((ih - 0x42800000u) & 0x80000000u) ^ (unsigned)(cj >> 32);
    ull cs = ((ull)csh << 32) | (ull)csl;
    ull inv = pk2(rsq(dl), rsq(dh));
    ull wg = mul2(cs, inv);
    g0 = fma2(wg, dx, g0);
    g1 = fma2(wg, dy, g1);
    g2 = fma2(wg, dz, g2);
}

// =====================================================================
// K3: persistent refine — R11 winning config (128 blocks x 512 thr,
// 2 rows/warp, cm rows in smem, LDS.128 loop, flag barrier).
// =====================================================================
#define RTH 512
#define BPB 32      // blocks per batch
#define SMEM_REFINE ((3 * S_ + 32 * S_) * (int)sizeof(float))

extern __shared__ float smref[];

__global__ __launch_bounds__(RTH, 1) void refine_kernel(float* __restrict__ out)
{
    float* xs  = smref;
    float* ys  = xs + S_;
    float* zs  = ys + S_;
    float* cmr = zs + S_;     // [32][1024]

    const int tid  = threadIdx.x;
    const int w    = tid >> 5;
    const int lane = tid & 31;
    const int b    = blockIdx.x >> 5;          // /BPB
    const int rbse = (blockIdx.x & 31) * 32;   // row base within batch
    const int rA   = rbse + w * 2;             // warp's rows: rA, rA+1

    // cache this warp's 2 contact-map rows (once; reused 50 steps)
    {
        const float4* sA = (const float4*)(g_cms + ((size_t)b * S_ + rA) * S_);
        const float4* sB = (const float4*)(g_cms + ((size_t)b * S_ + rA + 1) * S_);
        float4* dA = (float4*)(cmr + (size_t)(w * 2) * S_);
        float4* dB = (float4*)(cmr + (size_t)(w * 2 + 1) * S_);
        for (int k = lane; k < S_ / 4; k += 32) { dA[k] = sA[k]; dB[k] = sB[k]; }
    }

    // barrier state: my slot + per-lane peer slot (warp 0 only does waits)
    unsigned* myflag = &g_flag[(unsigned)blockIdx.x * 32u];
    unsigned* peerflag = &g_flag[(unsigned)(b * BPB + lane) * 32u];
    unsigned mybase = 0, peerbase = 0;
    if (tid == 0) mybase = ld_acq(myflag);
    if (w == 0) peerbase = ld_acq(peerflag);

    float m[2][3] = {{0,0,0},{0,0,0}};
    float v[2][3] = {{0,0,0},{0,0,0}};
    float b1t = 1.f, b2t = 1.f;

    PK K;
    K.M1   = pk2(-1.f, -1.f);
    K.EPS2 = pk2(1e-12f, 1e-12f);

    const float* cApt = cmr + (size_t)(w * 2) * S_;
    const float* cBpt = cApt + S_;

    for (int t = 1; t <= NSTEPS_; t++) {
        const float* xin = (t & 1) ? g_pA : g_pB;
        float* xout      = (t & 1) ? g_pB : g_pA;

        // reload positions (L2-coherent)
        {
            const float4* px = (const float4*)(xin + 0 * NROW + b * S_);
            const float4* py = (const float4*)(xin + 1 * NROW + b * S_);
            const float4* pz = (const float4*)(xin + 2 * NROW + b * S_);
            for (int i = tid; i < S_ / 4; i += RTH) {
                ((float4*)xs)[i] = __ldcg(px + i);
                ((float4*)ys)[i] = __ldcg(py + i);
                ((float4*)zs)[i] = __ldcg(pz + i);
            }
        }
        __syncthreads();

        const float axA = xs[rA],     ayA = ys[rA],     azA = zs[rA];
        const float axB = xs[rA + 1], ayB = ys[rA + 1], azB = zs[rA + 1];
        const ull xiA = pk2(axA, axA), yiA = pk2(ayA, ayA), ziA = pk2(azA, azA);
        const ull xiB = pk2(axB, axB), yiB = pk2(ayB, ayB), ziB = pk2(azB, azB);

        ull gA0 = 0, gA1 = 0, gA2 = 0;
        ull gB0 = 0, gB1 = 0, gB2 = 0;

#pragma unroll
        for (int it = 0; it < 8; it++) {
            const int j = it * 128 + lane * 4;
            const ulonglong2 xj  = *(const ulonglong2*)(xs + j);
            const ulonglong2 yj  = *(const ulonglong2*)(ys + j);
            const ulonglong2 zj  = *(const ulonglong2*)(zs + j);
            const ulonglong2 cjA = *(const ulonglong2*)(cApt + j);
            const ulonglong2 cjB = *(const ulonglong2*)(cBpt + j);

            pair_step(xj.x, yj.x, zj.x, cjA.x, xiA, yiA, ziA, gA0, gA1, gA2, K);
            pair_step(xj.x, yj.x, zj.x, cjB.x, xiB, yiB, ziB, gB0, gB1, gB2, K);
            pair_step(xj.y, yj.y, zj.y, cjA.y, xiA, yiA, ziA, gA0, gA1, gA2, K);
            pair_step(xj.y, yj.y, zj.y, cjB.y, xiB, yiB, ziB, gB0, gB1, gB2, K);
        }

        float gr[2][3];
        {
            float lo, hi;
            upk2(gA0, lo, hi); gr[0][0] = lo + hi;
            upk2(gA1, lo, hi); gr[0][1] = lo + hi;
            upk2(gA2, lo, hi); gr[0][2] = lo + hi;
            upk2(gB0, lo, hi); gr[1][0] = lo + hi;
            upk2(gB1, lo, hi); gr[1][1] = lo + hi;
            upk2(gB2, lo, hi); gr[1][2] = lo + hi;
        }
#pragma unroll
        for (int off = 16; off; off >>= 1) {
            gr[0][0] += __shfl_down_sync(0xffffffffu, gr[0][0], off);
            gr[0][1] += __shfl_down_sync(0xffffffffu, gr[0][1], off);
            gr[0][2] += __shfl_down_sync(0xffffffffu, gr[0][2], off);
            gr[1][0] += __shfl_down_sync(0xffffffffu, gr[1][0], off);
            gr[1][1] += __shfl_down_sync(0xffffffffu, gr[1][1], off);
            gr[1][2] += __shfl_down_sync(0xffffffffu, gr[1][2], off);
        }

        b1t *= BETA1_;
        b2t *= BETA2_;

        if (lane == 0) {
            const float c1f = 1.f / (1.f - b1t);
            const float c2f = 1.f / (1.f - b2t);
            float px[2][3] = {{axA, ayA, azA}, {axB, ayB, azB}};
#pragma unroll
            for (int r = 0; r < 2; r++) {
                float nv[3];
#pragma unroll
                for (int d = 0; d < 3; d++) {
                    m[r][d] = BETA1_ * m[r][d] + (1.f - BETA1_) * gr[r][d];
                    v[r][d] = BETA2_ * v[r][d] + (1.f - BETA2_) * gr[r][d] * gr[r][d];
                    float den = sqa(v[r][d] * c2f) + ADAM_EPS_;
                    nv[d] = px[r][d] - LR_ * (m[r][d] * c1f) * rcpa(den);
                }
                const int row = rA + r;
                if (t == NSTEPS_) {
                    size_t o = ((size_t)b * S_ + row) * 3;
                    out[o + 0] = nv[0];
                    out[o + 1] = nv[1];
                    out[o + 2] = nv[2];
                } else {
                    xout[0 * NROW + b * S_ + row] = nv[0];
                    xout[1 * NROW + b * S_ + row] = nv[1];
                    xout[2 * NROW + b * S_ + row] = nv[2];
                }
            }
        }

        if (t < NSTEPS_) {
            // bar.sync orders all warps' STGs before tid0's release-store
            __syncthreads();
            if (tid == 0) st_rel(myflag, mybase + (unsigned)t);
            if (w == 0) {
                const unsigned tgt = peerbase + (unsigned)t;
                while (ld_acq(peerflag) < tgt) { }
            }
            __syncthreads();
        }
    }
}

// =====================================================================
// host launcher (graph-capturable: kernel launches only, single stream)
// =====================================================================
extern "C" void kernel_launch(void* const* d_in, const int* in_sizes, int n_in,
                              void* d_out, int out_size)
{
    const float* bf  = (const float*)d_in[0];
    const float* cm  = (const float*)d_in[2];
    const float* Wb1 = (const float*)d_in[3];
    const float* bb1 = (const float*)d_in[4];
    const float* Wb2 = (const float*)d_in[5];
    const float* bb2 = (const float*)d_in[6];
    float* out = (float*)d_out;

    static int smem_set = 0;
    if (!smem_set) {
        cudaFuncSetAttribute(refine_kernel,
                             cudaFuncAttributeMaxDynamicSharedMemorySize, SMEM_REFINE);
        smem_set = 1;
    }

    gemm_relu_kernel<<<dim3(H_ / 64, NROW / 64), 256>>>(bf, Wb1, bb1);
    angles_delta_kernel<<<NROW, 128>>>(Wb2, bb2);
    cmsym_kernel<<<dim3(S_ / 32, S_ / 32, B_), dim3(32, 8)>>>(cm);
    cumsum_kernel<<<B_ * 3, S_>>>();
    refine_kernel<<<128, RTH, SMEM_REFINE>>>(out);
}

// round 16
// speedup vs baseline: 1.2332x; 1.0109x over previous
#include <cuda_runtime.h>
#include <math.h>

#define B_  4
#define S_  1024
#define D_  768
#define H_  384
#define NROW (B_*S_)            // 4096
#define BOND_ 3.8f
#define LR_ 0.01f
#define BETA1_ 0.9f
#define BETA2_ 0.999f
#define ADAM_EPS_ 1e-8f
#define NSTEPS_ 50

typedef unsigned long long ull;

// ---------- packed f32x2 helpers (Blackwell FFMA2 path) ----------
__device__ __forceinline__ ull pk2(float lo, float hi) {
    ull r; asm("mov.b64 %0,{%1,%2};" : "=l"(r) : "f"(lo), "f"(hi)); return r;
}
__device__ __forceinline__ void upk2(ull v, float& lo, float& hi) {
    asm("mov.b64 {%0,%1},%2;" : "=f"(lo), "=f"(hi) : "l"(v));
}
__device__ __forceinline__ ull fma2(ull a, ull b, ull c) {
    ull r; asm("fma.rn.f32x2 %0,%1,%2,%3;" : "=l"(r) : "l"(a), "l"(b), "l"(c)); return r;
}
__device__ __forceinline__ ull mul2(ull a, ull b) {
    ull r; asm("mul.rn.f32x2 %0,%1,%2;" : "=l"(r) : "l"(a), "l"(b)); return r;
}
__device__ __forceinline__ float rsq(float x) {
    float r; asm("rsqrt.approx.f32 %0,%1;" : "=f"(r) : "f"(x)); return r;
}
__device__ __forceinline__ float sqa(float x) {
    float r; asm("sqrt.approx.f32 %0,%1;" : "=f"(r) : "f"(x)); return r;
}
__device__ __forceinline__ float rcpa(float x) {
    float r; asm("rcp.approx.f32 %0,%1;" : "=f"(r) : "f"(x)); return r;
}

// ----- device scratch (no allocations allowed) -----
__device__ float g_part[6 * NROW * 2];         // per-(n-tile,row) phi/psi partials
__device__ float g_delta_unused;               // (kept layout minimal)
__device__ float g_pA[3 * NROW];               // ping-pong positions, SoA planes x|y|z
__device__ float g_pB[3 * NROW];
__device__ float g_cms[(size_t)B_ * S_ * S_];  // symmetrized + prescaled contact map (16 MB)
__device__ unsigned g_flag[128 * 32];          // per-block step flags, 128B-strided slots

__device__ __forceinline__ unsigned ld_acq(const unsigned* p) {
    unsigned v;
    asm volatile("ld.acquire.gpu.global.u32 %0,[%1];" : "=r"(v) : "l"(p) : "memory");
    return v;
}
__device__ __forceinline__ void st_rel(unsigned* p, unsigned v) {
    asm volatile("st.release.gpu.global.u32 [%0],%1;" :: "l"(p), "r"(v) : "memory");
}

// =====================================================================
// K1: fused GEMM + angles projection.
// Mainloop identical to the proven R11 GEMM. Epilogue: instead of
// storing h (6 MB), each thread projects its 4x4 register tile onto
// W2[:,0:2], 16-lane shuffle-reduce, and writes per-(n-tile,row)
// phi/psi partials to g_part (no atomics; 6 partials per row).
// =====================================================================
__global__ __launch_bounds__(256) void gemm_angles_kernel(
    const float* __restrict__ A, const float* __restrict__ W1,
    const float* __restrict__ b1, const float* __restrict__ W2)
{
    __shared__ float As[16][64];
    __shared__ float Bs[16][64];

    const int tid = threadIdx.x;
    const int tx = tid & 15;
    const int ty = tid >> 4;
    const int m0 = blockIdx.y * 64;
    const int n0 = blockIdx.x * 64;

    ull acc[4][2];
#pragma unroll
    for (int i = 0; i < 4; i++) { acc[i][0] = 0ull; acc[i][1] = 0ull; }

    for (int k0 = 0; k0 < D_; k0 += 16) {
        {
            int row = tid >> 2;
            int c4  = tid & 3;
            float4 a = *(const float4*)(A + (size_t)(m0 + row) * D_ + k0 + c4 * 4);
            As[c4 * 4 + 0][row] = a.x;
            As[c4 * 4 + 1][row] = a.y;
            As[c4 * 4 + 2][row] = a.z;
            As[c4 * 4 + 3][row] = a.w;
        }
        {
            int row = tid >> 4;
            int c4  = tid & 15;
            *(float4*)&Bs[row][c4 * 4] =
                *(const float4*)(W1 + (size_t)(k0 + row) * H_ + n0 + c4 * 4);
        }
        __syncthreads();

#pragma unroll
        for (int k = 0; k < 16; k++) {
            float a[4], bb[4];
            *(float4*)a  = *(const float4*)&As[k][ty * 4];
            *(float4*)bb = *(const float4*)&Bs[k][tx * 4];
            ull b01 = pk2(bb[0], bb[1]);
            ull b23 = pk2(bb[2], bb[3]);
#pragma unroll
            for (int i = 0; i < 4; i++) {
                ull ai = pk2(a[i], a[i]);
                acc[i][0] = fma2(ai, b01, acc[i][0]);
                acc[i][1] = fma2(ai, b23, acc[i][1]);
            }
        }
        __syncthreads();
    }

    // ---- fused epilogue: relu + project onto W2[:,0:2], reduce, store ----
    float4 bias = *(const float4*)(b1 + n0 + tx * 4);
    float w2p[4], w2q[4];
#pragma unroll
    for (int c = 0; c < 4; c++) {
        w2p[c] = __ldg(W2 + (size_t)(n0 + tx * 4 + c) * 3 + 0);
        w2q[c] = __ldg(W2 + (size_t)(n0 + tx * 4 + c) * 3 + 1);
    }

    float ph[4], ps[4];
#pragma unroll
    for (int i = 0; i < 4; i++) {
        float v0, v1, v2, v3;
        upk2(acc[i][0], v0, v1);
        upk2(acc[i][1], v2, v3);
        float h0 = fmaxf(v0 + bias.x, 0.f);
        float h1 = fmaxf(v1 + bias.y, 0.f);
        float h2 = fmaxf(v2 + bias.z, 0.f);
        float h3 = fmaxf(v3 + bias.w, 0.f);
        ph[i] = fmaf(h0, w2p[0], fmaf(h1, w2p[1], fmaf(h2, w2p[2], h3 * w2p[3])));
        ps[i] = fmaf(h0, w2q[0], fmaf(h1, w2q[1], fmaf(h2, w2q[2], h3 * w2q[3])));
    }
    // reduce across the 16 tx lanes (lanes 0-15 / 16-31 hold distinct ty)
#pragma unroll
    for (int off = 8; off; off >>= 1) {
#pragma unroll
        for (int i = 0; i < 4; i++) {
            ph[i] += __shfl_down_sync(0xffffffffu, ph[i], off);
            ps[i] += __shfl_down_sync(0xffffffffu, ps[i], off);
        }
    }
    if ((tid & 15) == 0) {
        const size_t ntbase = (size_t)blockIdx.x * NROW;
#pragma unroll
        for (int i = 0; i < 4; i++) {
            int row = m0 + ty * 4 + i;
            ((float2*)g_part)[ntbase + row] = make_float2(ph[i], ps[i]);
        }
    }
}

// =====================================================================
// K2: fused delta + cumsum. 12 blocks (batch, dim) x 1024 threads.
// Sums the 6 phi/psi partials + bias, sincos, takes the dim component,
// then an inclusive block scan -> g_pA SoA planes.
// =====================================================================
__global__ __launch_bounds__(1024) void cumdelta_kernel(const float* __restrict__ b2)
{
    const int b   = blockIdx.x / 3;
    const int dim = blockIdx.x % 3;
    const int s   = threadIdx.x;
    const int row = b * S_ + s;

    float v;
    if (s == 0) {
        v = 0.f;
    } else {
        float phi = b2[0], psi = b2[1];
#pragma unroll
        for (int p = 0; p < 6; p++) {
            float2 pp = ((const float2*)g_part)[(size_t)p * NROW + row];
            phi += pp.x;
            psi += pp.y;
        }
        float sp, cp, ss, cs;
        sincosf(phi, &sp, &cp);
        sincosf(psi, &ss, &cs);
        v = (dim == 0) ? BOND_ * cp * cs
          : (dim == 1) ? BOND_ * sp * cs
                       : BOND_ * ss;
    }

    int lane = s & 31, w = s >> 5;
#pragma unroll
    for (int off = 1; off < 32; off <<= 1) {
        float n = __shfl_up_sync(0xffffffffu, v, off);
        if (lane >= off) v += n;
    }
    __shared__ float wsum[32];
    if (lane == 31) wsum[w] = v;
    __syncthreads();
    if (w == 0) {
        float t = wsum[lane];
#pragma unroll
        for (int off = 1; off < 32; off <<= 1) {
            float n = __shfl_up_sync(0xffffffffu, t, off);
            if (lane >= off) t += n;
        }
        wsum[lane] = t;
    }
    __syncthreads();
    float excl = (w == 0) ? 0.f : wsum[w - 1];
    g_pA[dim * NROW + row] = v + excl;
}

// =====================================================================
// K0: cm_sym[b,i,j] = (cm[b,i,j] + cm[b,j,i]) / (B*S*S)
// =====================================================================
__global__ void cmsym_kernel(const float* __restrict__ cm)
{
    __shared__ float ts[32][33];
    const int b  = blockIdx.z;
    const int i0 = blockIdx.y * 32;
    const int j0 = blockIdx.x * 32;
    const float* cb = cm + (size_t)b * S_ * S_;
    float* ob = g_cms + (size_t)b * S_ * S_;
    const int tx = threadIdx.x, ty = threadIdx.y;
    const float invN = 1.0f / (float)((size_t)B_ * S_ * S_);

#pragma unroll
    for (int r = ty; r < 32; r += 8)
        ts[r][tx] = cb[(size_t)(j0 + r) * S_ + i0 + tx];
    __syncthreads();
#pragma unroll
    for (int r = ty; r < 32; r += 8)
        ob[(size_t)(i0 + r) * S_ + j0 + tx] =
            (cb[(size_t)(i0 + r) * S_ + j0 + tx] + ts[tx][r]) * invN;
}

// =====================================================================
// one (row, packed-j-pair) gradient step — f32x2; integer sign trick
// =====================================================================
struct PK {
    ull M1, EPS2;
};

__device__ __forceinline__ void pair_step(
    ull xj, ull yj, ull zj, ull cj,
    ull xi, ull yi, ull zi,
    ull& g0, ull& g1, ull& g2, const PK& K)
{
    ull dx = fma2(K.M1, xj, xi);
    ull dy = fma2(K.M1, yj, yi);
    ull dz = fma2(K.M1, zj, zi);
    ull d2 = fma2(dx, dx, K.EPS2);
    d2 = fma2(dy, dy, d2);
    d2 = fma2(dz, dz, d2);
    float dl, dh; upk2(d2, dl, dh);
    unsigned il = __float_as_uint(dl), ih = __float_as_uint(dh);
    unsigned csl = ((il - 0x42800000u) & 0x80000000u) ^ (unsigned)cj;
    unsigned csh = ((ih - 0x42800000u) & 0x80000000u) ^ (unsigned)(cj >> 32);
    ull cs = ((ull)csh << 32) | (ull)csl;
    ull inv = pk2(rsq(dl), rsq(dh));
    ull wg = mul2(cs, inv);
    g0 = fma2(wg, dx, g0);
    g1 = fma2(wg, dy, g1);
    g2 = fma2(wg, dz, g2);
}

// =====================================================================
// K3: persistent refine — R11 winning config, UNCHANGED.
// =====================================================================
#define RTH 512
#define BPB 32      // blocks per batch
#define SMEM_REFINE ((3 * S_ + 32 * S_) * (int)sizeof(float))

extern __shared__ float smref[];

__global__ __launch_bounds__(RTH, 1) void refine_kernel(float* __restrict__ out)
{
    float* xs  = smref;
    float* ys  = xs + S_;
    float* zs  = ys + S_;
    float* cmr = zs + S_;     // [32][1024]

    const int tid  = threadIdx.x;
    const int w    = tid >> 5;
    const int lane = tid & 31;
    const int b    = blockIdx.x >> 5;          // /BPB
    const int rbse = (blockIdx.x & 31) * 32;   // row base within batch
    const int rA   = rbse + w * 2;             // warp's rows: rA, rA+1

    // cache this warp's 2 contact-map rows (once; reused 50 steps)
    {
        const float4* sA = (const float4*)(g_cms + ((size_t)b * S_ + rA) * S_);
        const float4* sB = (const float4*)(g_cms + ((size_t)b * S_ + rA + 1) * S_);
        float4* dA = (float4*)(cmr + (size_t)(w * 2) * S_);
        float4* dB = (float4*)(cmr + (size_t)(w * 2 + 1) * S_);
        for (int k = lane; k < S_ / 4; k += 32) { dA[k] = sA[k]; dB[k] = sB[k]; }
    }

    // barrier state: my slot + per-lane peer slot (warp 0 only does waits)
    unsigned* myflag = &g_flag[(unsigned)blockIdx.x * 32u];
    unsigned* peerflag = &g_flag[(unsigned)(b * BPB + lane) * 32u];
    unsigned mybase = 0, peerbase = 0;
    if (tid == 0) mybase = ld_acq(myflag);
    if (w == 0) peerbase = ld_acq(peerflag);

    float m[2][3] = {{0,0,0},{0,0,0}};
    float v[2][3] = {{0,0,0},{0,0,0}};
    float b1t = 1.f, b2t = 1.f;

    PK K;
    K.M1   = pk2(-1.f, -1.f);
    K.EPS2 = pk2(1e-12f, 1e-12f);

    const float* cApt = cmr + (size_t)(w * 2) * S_;
    const float* cBpt = cApt + S_;

    for (int t = 1; t <= NSTEPS_; t++) {
        const float* xin = (t & 1) ? g_pA : g_pB;
        float* xout      = (t & 1) ? g_pB : g_pA;

        // reload positions (L2-coherent)
        {
            const float4* px = (const float4*)(xin + 0 * NROW + b * S_);
            const float4* py = (const float4*)(xin + 1 * NROW + b * S_);
            const float4* pz = (const float4*)(xin + 2 * NROW + b * S_);
            for (int i = tid; i < S_ / 4; i += RTH) {
                ((float4*)xs)[i] = __ldcg(px + i);
                ((float4*)ys)[i] = __ldcg(py + i);
                ((float4*)zs)[i] = __ldcg(pz + i);
            }
        }
        __syncthreads();

        const float axA = xs[rA],     ayA = ys[rA],     azA = zs[rA];
        const float axB = xs[rA + 1], ayB = ys[rA + 1], azB = zs[rA + 1];
        const ull xiA = pk2(axA, axA), yiA = pk2(ayA, ayA), ziA = pk2(azA, azA);
        const ull xiB = pk2(axB, axB), yiB = pk2(ayB, ayB), ziB = pk2(azB, azB);

        ull gA0 = 0, gA1 = 0, gA2 = 0;
        ull gB0 = 0, gB1 = 0, gB2 = 0;

#pragma unroll
        for (int it = 0; it < 8; it++) {
            const int j = it * 128 + lane * 4;
            const ulonglong2 xj  = *(const ulonglong2*)(xs + j);
            const ulonglong2 yj  = *(const ulonglong2*)(ys + j);
            const ulonglong2 zj  = *(const ulonglong2*)(zs + j);
            const ulonglong2 cjA = *(const ulonglong2*)(cApt + j);
            const ulonglong2 cjB = *(const ulonglong2*)(cBpt + j);

            pair_step(xj.x, yj.x, zj.x, cjA.x, xiA, yiA, ziA, gA0, gA1, gA2, K);
            pair_step(xj.x, yj.x, zj.x, cjB.x, xiB, yiB, ziB, gB0, gB1, gB2, K);
            pair_step(xj.y, yj.y, zj.y, cjA.y, xiA, yiA, ziA, gA0, gA1, gA2, K);
            pair_step(xj.y, yj.y, zj.y, cjB.y, xiB, yiB, ziB, gB0, gB1, gB2, K);
        }

        float gr[2][3];
        {
            float lo, hi;
            upk2(gA0, lo, hi); gr[0][0] = lo + hi;
            upk2(gA1, lo, hi); gr[0][1] = lo + hi;
            upk2(gA2, lo, hi); gr[0][2] = lo + hi;
            upk2(gB0, lo, hi); gr[1][0] = lo + hi;
            upk2(gB1, lo, hi); gr[1][1] = lo + hi;
            upk2(gB2, lo, hi); gr[1][2] = lo + hi;
        }
#pragma unroll
        for (int off = 16; off; off >>= 1) {
            gr[0][0] += __shfl_down_sync(0xffffffffu, gr[0][0], off);
            gr[0][1] += __shfl_down_sync(0xffffffffu, gr[0][1], off);
            gr[0][2] += __shfl_down_sync(0xffffffffu, gr[0][2], off);
            gr[1][0] += __shfl_down_sync(0xffffffffu, gr[1][0], off);
            gr[1][1] += __shfl_down_sync(0xffffffffu, gr[1][1], off);
            gr[1][2] += __shfl_down_sync(0xffffffffu, gr[1][2], off);
        }

        b1t *= BETA1_;
        b2t *= BETA2_;

        if (lane == 0) {
            const float c1f = 1.f / (1.f - b1t);
            const float c2f = 1.f / (1.f - b2t);
            float px[2][3] = {{axA, ayA, azA}, {axB, ayB, azB}};
#pragma unroll
            for (int r = 0; r < 2; r++) {
                float nv[3];
#pragma unroll
                for (int d = 0; d < 3; d++) {
                    m[r][d] = BETA1_ * m[r][d] + (1.f - BETA1_) * gr[r][d];
                    v[r][d] = BETA2_ * v[r][d] + (1.f - BETA2_) * gr[r][d] * gr[r][d];
                    float den = sqa(v[r][d] * c2f) + ADAM_EPS_;
                    nv[d] = px[r][d] - LR_ * (m[r][d] * c1f) * rcpa(den);
                }
                const int row = rA + r;
                if (t == NSTEPS_) {
                    size_t o = ((size_t)b * S_ + row) * 3;
                    out[o + 0] = nv[0];
                    out[o + 1] = nv[1];
                    out[o + 2] = nv[2];
                } else {
                    xout[0 * NROW + b * S_ + row] = nv[0];
                    xout[1 * NROW + b * S_ + row] = nv[1];
                    xout[2 * NROW + b * S_ + row] = nv[2];
                }
            }
        }

        if (t < NSTEPS_) {
            // bar.sync orders all warps' STGs before tid0's release-store
            __syncthreads();
            if (tid == 0) st_rel(myflag, mybase + (unsigned)t);
            if (w == 0) {
                const unsigned tgt = peerbase + (unsigned)t;
                while (ld_acq(peerflag) < tgt) { }
            }
            __syncthreads();
        }
    }
}

// =====================================================================
// host launcher (graph-capturable: kernel launches only, single stream)
// =====================================================================
extern "C" void kernel_launch(void* const* d_in, const int* in_sizes, int n_in,
                              void* d_out, int out_size)
{
    const float* bf  = (const float*)d_in[0];
    const float* cm  = (const float*)d_in[2];
    const float* Wb1 = (const float*)d_in[3];
    const float* bb1 = (const float*)d_in[4];
    const float* Wb2 = (const float*)d_in[5];
    const float* bb2 = (const float*)d_in[6];
    float* out = (float*)d_out;

    static int smem_set = 0;
    if (!smem_set) {
        cudaFuncSetAttribute(refine_kernel,
                             cudaFuncAttributeMaxDynamicSharedMemorySize, SMEM_REFINE);
        smem_set = 1;
    }

    gemm_angles_kernel<<<dim3(H_ / 64, NROW / 64), 256>>>(bf, Wb1, bb1, Wb2);
    cumdelta_kernel<<<B_ * 3, S_>>>(bb2);
    cmsym_kernel<<<dim3(S_ / 32, S_ / 32, B_), dim3(32, 8)>>>(cm);
    refine_kernel<<<128, RTH, SMEM_REFINE>>>(out);
}